// round 3
// baseline (speedup 1.0000x reference)
#include <cuda_runtime.h>
#include <math.h>

#define NIMG 4
#define NCLS 19
#define HWPIX 589824            // 768*768
#define NTOT (NIMG * HWPIX)
#define IGN 255
#define EDGE_T 0.8f
#define PPT 8                   // pixels per thread in k_main / k_hist

// ---------------- device-global scratch (no allocations allowed) ----------------
// Zero-initialized at module load (first correctness run); k_final resets them
// after producing the output so every graph replay starts clean.
__device__ int    g_seg_bins[NIMG * NCLS];
__device__ int    g_att_bins[NIMG * NCLS];
__device__ int    g_pos;
__device__ int    g_neg;
// layout: [0..3] num_seg, [4..7] den_seg, [8..11] num_att, [12..15] den_att, [16] bce_sum
__device__ double g_acc[NIMG * 4 + 1];

// ---------------- kernel 1: per-image class histograms + global pos/neg counts ----------------
__global__ void __launch_bounds__(256) k_hist(const int* __restrict__ seg,
                                              const float* __restrict__ edge,
                                              const int* __restrict__ em) {
    __shared__ int sb[NCLS], ab[NCLS], spn[2];
    int tid = threadIdx.x;
    if (tid < NCLS) { sb[tid] = 0; ab[tid] = 0; }
    if (tid < 2) spn[tid] = 0;
    __syncthreads();

    const int BPI = HWPIX / (256 * PPT);   // 288 blocks per image
    int n    = blockIdx.x / BPI;
    int base = n * HWPIX + (blockIdx.x % BPI) * (256 * PPT) + tid * PPT;

    int4   t0 = *(const int4*)(seg + base);
    int4   t1 = *(const int4*)(seg + base + 4);
    float4 e0 = *(const float4*)(edge + base);
    float4 e1 = *(const float4*)(edge + base + 4);
    int4   m0 = *(const int4*)(em + base);
    int4   m1 = *(const int4*)(em + base + 4);

    int   tv[PPT] = {t0.x, t0.y, t0.z, t0.w, t1.x, t1.y, t1.z, t1.w};
    float ev[PPT] = {e0.x, e0.y, e0.z, e0.w, e1.x, e1.y, e1.z, e1.w};
    int   mv[PPT] = {m0.x, m0.y, m0.z, m0.w, m1.x, m1.y, m1.z, m1.w};

    int lpos = 0, lneg = 0;
#pragma unroll
    for (int k = 0; k < PPT; k++) {
        int t = tv[k];
        if ((unsigned)t < (unsigned)NCLS) {
            atomicAdd(&sb[t], 1);
            if (ev[k] > EDGE_T) atomicAdd(&ab[t], 1);
        }
        lpos += (mv[k] == 1);
        lneg += (mv[k] == 0);
    }
    for (int o = 16; o; o >>= 1) {
        lpos += __shfl_down_sync(0xffffffffu, lpos, o);
        lneg += __shfl_down_sync(0xffffffffu, lneg, o);
    }
    if ((tid & 31) == 0) { atomicAdd(&spn[0], lpos); atomicAdd(&spn[1], lneg); }
    __syncthreads();

    if (tid < NCLS) {
        atomicAdd(&g_seg_bins[n * NCLS + tid], sb[tid]);
        atomicAdd(&g_att_bins[n * NCLS + tid], ab[tid]);
    }
    if (tid == 0) atomicAdd(&g_pos, spn[0]);
    if (tid == 1) atomicAdd(&g_neg, spn[1]);
}

// ---------------- kernel 2: main pass (HBM-bound: reads segin once) ----------------
// 256 threads x 8 pixels; channel loop batched 4 channels at a time for MLP.
__global__ void __launch_bounds__(256) k_main(const float* __restrict__ segin,
                                              const float* __restrict__ edgein,
                                              const int* __restrict__ segmask,
                                              const int* __restrict__ emask) {
    const int BPI = HWPIX / (256 * PPT);   // 288
    int n   = blockIdx.x / BPI;
    int tid = threadIdx.x;

    // Per-block weight recomputation from bins (L2-hit loads; replaces k_weights)
    __shared__ float swseg[NCLS], swatt[NCLS], swe[2];
    if (tid < NCLS) {
        float ssum = 0.f, asum = 0.f;
        for (int c = 0; c < NCLS; c++) {
            ssum += (float)g_seg_bins[n * NCLS + c];
            asum += (float)g_att_bins[n * NCLS + c];
        }
        int sc = g_seg_bins[n * NCLS + tid], ac = g_att_bins[n * NCLS + tid];
        swseg[tid] = sc ? (2.0f - (float)sc / ssum) : 1.0f;
        swatt[tid] = ac ? (2.0f - (float)ac / asum) : 1.0f;
    }
    if (tid == 32) {
        float p = (float)g_pos, nn = (float)g_neg;
        float s = p + nn;
        swe[0] = nn / s;   // weight at t==1
        swe[1] = p / s;    // weight at t==0
    }
    __syncthreads();

    int local = (blockIdx.x % BPI) * (256 * PPT) + tid * PPT;
    int p     = n * HWPIX + local;

    int4   t0 = *(const int4*)(segmask + p);
    int4   t1 = *(const int4*)(segmask + p + 4);
    float4 e0 = *(const float4*)(edgein + p);
    float4 e1 = *(const float4*)(edgein + p + 4);
    int4   m0 = *(const int4*)(emask + p);
    int4   m1 = *(const int4*)(emask + p + 4);

    int   tv[PPT] = {t0.x, t0.y, t0.z, t0.w, t1.x, t1.y, t1.z, t1.w};
    float ev[PPT] = {e0.x, e0.y, e0.z, e0.w, e1.x, e1.y, e1.z, e1.w};
    int   mv[PPT] = {m0.x, m0.y, m0.z, m0.w, m1.x, m1.y, m1.z, m1.w};
    int   tcls[PPT];
#pragma unroll
    for (int i = 0; i < PPT; i++) tcls[i] = min(max(tv[i], 0), NCLS - 1);

    const float* sp = segin + (size_t)n * (size_t)NCLS * (size_t)HWPIX + (size_t)local;

    float s[PPT], xt[PPT];
#pragma unroll
    for (int i = 0; i < PPT; i++) { s[i] = 0.f; xt[i] = 0.f; }

#pragma unroll
    for (int c0 = 0; c0 < NCLS; c0 += 4) {
        // batch loads for 4 channels (8 float4 in flight) before any MUFU work
        float4 a[4][2];
#pragma unroll
        for (int j = 0; j < 4; j++) {
            int c = c0 + j;
            if (c < NCLS) {
                a[j][0] = *(const float4*)(sp + (size_t)c * HWPIX);
                a[j][1] = *(const float4*)(sp + (size_t)c * HWPIX + 4);
            }
        }
#pragma unroll
        for (int j = 0; j < 4; j++) {
            int c = c0 + j;
            if (c < NCLS) {
                float xv[PPT] = {a[j][0].x, a[j][0].y, a[j][0].z, a[j][0].w,
                                 a[j][1].x, a[j][1].y, a[j][1].z, a[j][1].w};
#pragma unroll
                for (int i = 0; i < PPT; i++) {
                    s[i] += __expf(xv[i]);
                    xt[i] = (c == tcls[i]) ? xv[i] : xt[i];
                }
            }
        }
    }

    float anum = 0.f, aden = 0.f, bnum = 0.f, bden = 0.f, bce = 0.f;
#pragma unroll
    for (int i = 0; i < PPT; i++) {
        float nll = __logf(s[i]) - xt[i];        // = -log_softmax[target]
        bool  v   = (tv[i] != IGN);
        float w   = v ? swseg[tcls[i]] : 0.0f;
        anum += w * nll;  aden += w;
        bool  va  = v && (ev[i] > EDGE_T);
        float wa  = va ? swatt[tcls[i]] : 0.0f;
        bnum += wa * nll; bden += wa;
        float xx  = ev[i];
        float tf  = (float)mv[i];
        float we  = (mv[i] == 1) ? swe[0] : ((mv[i] == 0) ? swe[1] : 0.0f);
        float b   = fmaxf(xx, 0.0f) - xx * tf + log1pf(__expf(-fabsf(xx)));
        bce += we * b;
    }

    // block reduction of 5 floats
    __shared__ float red[8][5];
    float vals[5] = {anum, aden, bnum, bden, bce};
#pragma unroll
    for (int k = 0; k < 5; k++) {
        float v = vals[k];
        for (int o = 16; o; o >>= 1) v += __shfl_down_sync(0xffffffffu, v, o);
        if ((tid & 31) == 0) red[tid >> 5][k] = v;
    }
    __syncthreads();
    if (tid == 0) {
        double a[5] = {0, 0, 0, 0, 0};
#pragma unroll
        for (int w = 0; w < 8; w++)
#pragma unroll
            for (int k = 0; k < 5; k++) a[k] += (double)red[w][k];
        atomicAdd(&g_acc[0 * NIMG + n], a[0]);
        atomicAdd(&g_acc[1 * NIMG + n], a[1]);
        atomicAdd(&g_acc[2 * NIMG + n], a[2]);
        atomicAdd(&g_acc[3 * NIMG + n], a[3]);
        atomicAdd(&g_acc[4 * NIMG],     a[4]);
    }
}

// ---------------- kernel 3: finalize scalar, then reset scratch for next replay ----------------
__global__ void k_final(float* out) {
    int i = threadIdx.x;
    if (i == 0) {
        double segl = 0.0, attl = 0.0;
        for (int k = 0; k < NIMG; k++) {
            segl += g_acc[k]            / g_acc[NIMG + k];
            attl += g_acc[2 * NIMG + k] / g_acc[3 * NIMG + k];
        }
        double edgel = 0.3 * (g_acc[4 * NIMG] / (double)NTOT);
        out[0] = (float)(1.0 * segl + edgel + 0.1 * attl);
    }
    __syncthreads();
    // reset scratch for next graph replay
    if (i < NIMG * NCLS) { g_seg_bins[i] = 0; g_att_bins[i] = 0; }
    if (i < NIMG * 4 + 1) g_acc[i] = 0.0;
    if (i == 0) { g_pos = 0; g_neg = 0; }
}

extern "C" void kernel_launch(void* const* d_in, const int* in_sizes, int n_in,
                              void* d_out, int out_size) {
    const float* segin   = (const float*)d_in[0];
    const float* edgein  = (const float*)d_in[1];
    const int*   segmask = (const int*)d_in[2];
    const int*   emask   = (const int*)d_in[3];

    k_hist <<<NIMG * (HWPIX / (256 * PPT)), 256>>>(segmask, edgein, emask);
    k_main <<<NIMG * (HWPIX / (256 * PPT)), 256>>>(segin, edgein, segmask, emask);
    k_final<<<1, 128>>>((float*)d_out);
}